// round 14
// baseline (speedup 1.0000x reference)
#include <cuda_runtime.h>
#include <math.h>
#include <stdint.h>

// Problem constants
#define B_ 256
#define N_ 256
#define C_ 768
#define A_ 10
#define H_ 8
#define E_ 4
#define D_ 96
#define SCALE_ 0.10206207261596575f   // 96^-0.5
#define SPLITS_ 4                     // attention N-splits

// ---------------- device scratch (no allocations allowed) ----------------
__device__ float g_qb[B_*C_];
__device__ float g_qhat[B_*H_*C_];
__device__ float g_xbar[B_*H_*C_];
__device__ float g_o[B_*C_];
__device__ float g_uP[(B_+A_)*C_];
__device__ float g_Yw[(B_+A_)*E_*C_];
__device__ float g_gate[(B_+A_)*E_];
__device__ float g_dr[(B_+A_)];
__device__ float g_pacc[SPLITS_*B_*H_*C_];
__device__ float2 g_pms[SPLITS_*B_*H_];

// ---------------- cp.async helpers ---------------------------------------
__device__ __forceinline__ void cp_async16(void* smem_dst, const void* gmem_src) {
    uint32_t d = (uint32_t)__cvta_generic_to_shared(smem_dst);
    asm volatile("cp.async.cg.shared.global [%0], [%1], 16;\n" :: "r"(d), "l"(gmem_src));
}
__device__ __forceinline__ void cp_async16z(void* smem_dst, const void* gmem_src, bool full) {
    uint32_t d = (uint32_t)__cvta_generic_to_shared(smem_dst);
    int sz = full ? 16 : 0;
    asm volatile("cp.async.cg.shared.global [%0], [%1], 16, %2;\n"
                 :: "r"(d), "l"(gmem_src), "r"(sz));
}
#define CP_COMMIT() asm volatile("cp.async.commit_group;\n" ::: "memory")
#define CP_WAIT(n)  asm volatile("cp.async.wait_group %0;\n" :: "n"(n) : "memory")

// ---------------- tf32 helpers --------------------------------------------
__device__ __forceinline__ uint32_t f2tf(float f) {
    uint32_t r;
    asm("cvt.rna.tf32.f32 %0, %1;" : "=r"(r) : "f"(f));
    return r;
}
__device__ __forceinline__ void mma_tf32(float* c,
    uint32_t a0, uint32_t a1, uint32_t a2, uint32_t a3,
    uint32_t b0, uint32_t b1)
{
    asm volatile(
        "mma.sync.aligned.m16n8k8.row.col.f32.tf32.tf32.f32 "
        "{%0,%1,%2,%3}, {%4,%5,%6,%7}, {%8,%9}, {%0,%1,%2,%3};"
        : "+f"(c[0]), "+f"(c[1]), "+f"(c[2]), "+f"(c[3])
        : "r"(a0), "r"(a1), "r"(a2), "r"(a3), "r"(b0), "r"(b1));
}

// ---------------- tf32 GEMM, cp.async double-buffered ---------------------
// BM=BN=64, BK=16, 128 threads (2x2 warps, 32x32 warp tiles).
// TRANSB=true : W is [N,K] row-major (torch Linear weight)
// TRANSB=false: W is [K,N] row-major
// Requires K % 16 == 0, N % 4 == 0.
template<bool TRANSB, bool HAS_BIAS, bool HAS_EXTRA>
__global__ void __launch_bounds__(128) gemm_tc_k(
    int M, int N, int K,
    const float* __restrict__ X, int lda, int sx,
    const float* __restrict__ W, int ldw, int sw,
    float* __restrict__ Y, int ldy, int sy,
    const float* __restrict__ bias, int sb,
    const float* __restrict__ extra, int lde)
{
    constexpr int BM = 64, BN = 64, BK = 16;
    int batch = blockIdx.z;
    X += (size_t)batch * sx;
    W += (size_t)batch * sw;

    // A: [buf][m][k] stride 20 (conflict-free fragment loads)
    // B: TRANSB -> [buf][n*20 + k] ; !TRANSB -> [buf][k*68 + n]
    __shared__ float As[2][BM][20];
    __shared__ float Bs[2][1280];

    int tid = threadIdx.x;
    int lane = tid & 31, warp = tid >> 5;
    int wm = warp >> 1, wn = warp & 1;
    int qr = lane & 3, qc = lane >> 2;
    int m0 = blockIdx.y * BM, n0 = blockIdx.x * BN;

    float acc[2][4][4];
#pragma unroll
    for (int i = 0; i < 2; i++)
#pragma unroll
        for (int j = 0; j < 4; j++)
#pragma unroll
            for (int l = 0; l < 4; l++) acc[i][j][l] = 0.f;

    int nIter = K / BK;

    auto issue = [&](int it) {
        int buf = it & 1;
        int kb = it * BK;
#pragma unroll
        for (int j = 0; j < 2; j++) {
            int idx = tid + j * 128;
            int mi = idx >> 2, kq = idx & 3;
            int mm = m0 + mi;
            bool ok = mm < M;
            const float* s = X + (size_t)(ok ? mm : 0) * lda + kb + kq * 4;
            cp_async16z(&As[buf][mi][kq * 4], s, ok);
        }
        if (TRANSB) {
#pragma unroll
            for (int j = 0; j < 2; j++) {
                int idx = tid + j * 128;
                int ni = idx >> 2, kq = idx & 3;
                int nn = n0 + ni;
                bool ok = nn < N;
                const float* s = W + (size_t)(ok ? nn : 0) * ldw + kb + kq * 4;
                cp_async16z(&Bs[buf][ni * 20 + kq * 4], s, ok);
            }
        } else {
#pragma unroll
            for (int j = 0; j < 2; j++) {
                int idx = tid + j * 128;
                int kr = idx >> 4, nq = idx & 15;
                int nn = n0 + nq * 4;
                bool ok = nn < N;
                const float* s = W + (size_t)(kb + kr) * ldw + (ok ? nn : 0);
                cp_async16z(&Bs[buf][kr * 68 + nq * 4], s, ok);
            }
        }
        CP_COMMIT();
    };

    issue(0);
    for (int it = 0; it < nIter; it++) {
        if (it + 1 < nIter) issue(it + 1);
        else CP_COMMIT();                  // empty group keeps count
        CP_WAIT(1);
        __syncthreads();
        int buf = it & 1;
#pragma unroll
        for (int kk = 0; kk < BK; kk += 8) {
            uint32_t af[2][4];
#pragma unroll
            for (int mi2 = 0; mi2 < 2; mi2++) {
                int rb = wm * 32 + mi2 * 16 + qc;
                af[mi2][0] = f2tf(As[buf][rb][kk + qr]);
                af[mi2][1] = f2tf(As[buf][rb + 8][kk + qr]);
                af[mi2][2] = f2tf(As[buf][rb][kk + qr + 4]);
                af[mi2][3] = f2tf(As[buf][rb + 8][kk + qr + 4]);
            }
            uint32_t bf[4][2];
#pragma unroll
            for (int ni = 0; ni < 4; ni++) {
                int cb = wn * 32 + ni * 8 + qc;
                if (TRANSB) {
                    bf[ni][0] = f2tf(Bs[buf][cb * 20 + kk + qr]);
                    bf[ni][1] = f2tf(Bs[buf][cb * 20 + kk + qr + 4]);
                } else {
                    bf[ni][0] = f2tf(Bs[buf][(kk + qr) * 68 + cb]);
                    bf[ni][1] = f2tf(Bs[buf][(kk + qr + 4) * 68 + cb]);
                }
            }
#pragma unroll
            for (int mi2 = 0; mi2 < 2; mi2++)
#pragma unroll
                for (int ni = 0; ni < 4; ni++)
                    mma_tf32(acc[mi2][ni],
                             af[mi2][0], af[mi2][1], af[mi2][2], af[mi2][3],
                             bf[ni][0], bf[ni][1]);
        }
        __syncthreads();
    }

    // ---- epilogue ----
    Y += (size_t)batch * sy;
#pragma unroll
    for (int mi2 = 0; mi2 < 2; mi2++) {
#pragma unroll
        for (int ni = 0; ni < 4; ni++) {
            int r0 = m0 + wm * 32 + mi2 * 16 + qc;
            int c0 = n0 + wn * 32 + ni * 8 + 2 * qr;
#pragma unroll
            for (int half = 0; half < 2; half++) {
                int r = r0 + half * 8;
                if (r >= M) continue;
#pragma unroll
                for (int cc = 0; cc < 2; cc++) {
                    int c = c0 + cc;
                    if (c >= N) continue;
                    float v = acc[mi2][ni][half * 2 + cc];
                    if (HAS_BIAS)  v += bias[(size_t)batch * sb + c];
                    if (HAS_EXTRA) v += extra[(size_t)r * lde + c];
                    Y[(size_t)r * ldy + c] = v;
                }
            }
        }
    }
}

// ---------------- attention: split-N partial pass, 4-stage pipeline -------
__global__ void __launch_bounds__(256) attn_part_k(
    const float* __restrict__ xg, const float* __restrict__ qhat,
    float* __restrict__ pacc, float2* __restrict__ pms)
{
    int s = blockIdx.x, b = blockIdx.y;
    int tid = threadIdx.x, w = tid >> 5, lane = tid & 31;
    __shared__ __align__(16) float qh[H_ * C_];       // 24 KB
    __shared__ __align__(16) float xs[4][4][C_];      // 48 KB (4-stage, 4-row tiles)

    const float* xb = xg + ((size_t)b * N_ + (size_t)s * 64) * C_;

    auto issue = [&](int t) {
        int buf = t & 3;
        const float* src0 = xb + (size_t)t * 4 * C_;
#pragma unroll
        for (int i = 0; i < 3; i++) {
            int idx = tid + i * 256;
            int r = idx / 192, c4 = idx - r * 192;
            cp_async16(&xs[buf][r][c4 * 4], src0 + (size_t)r * C_ + c4 * 4);
        }
        CP_COMMIT();
    };

    issue(0); issue(1); issue(2);
    {
        const float4* src = (const float4*)(qhat + (size_t)b * H_ * C_);
        float4* dst = (float4*)qh;
#pragma unroll
        for (int i = 0; i < 6; i++) dst[tid + i * 256] = src[tid + i * 256];
    }

    const float* qw = qh + w * C_;
    float m = -INFINITY, ssum = 0.f;
    float acc[24];
#pragma unroll
    for (int j = 0; j < 24; j++) acc[j] = 0.f;

    for (int t = 0; t < 16; t++) {
        if (t + 3 < 16) issue(t + 3);
        else CP_COMMIT();                  // empty group keeps count
        CP_WAIT(3);
        __syncthreads();
        const int buf = t & 3;
#pragma unroll
        for (int r = 0; r < 4; r++) {
            const float* xr = xs[buf][r];
            float part = 0.f;
#pragma unroll
            for (int j = 0; j < 24; j++)
                part = fmaf(qw[j * 32 + lane], xr[j * 32 + lane], part);
#pragma unroll
            for (int o = 16; o; o >>= 1)
                part += __shfl_xor_sync(0xffffffffu, part, o);
            float l = part * SCALE_;
            if (l > m) {
                float corr = __expf(m - l);
                ssum = ssum * corr + 1.f;
#pragma unroll
                for (int j = 0; j < 24; j++)
                    acc[j] = fmaf(acc[j], corr, xr[j * 32 + lane]);
                m = l;
            } else {
                float p = __expf(l - m);
                ssum += p;
#pragma unroll
                for (int j = 0; j < 24; j++)
                    acc[j] = fmaf(p, xr[j * 32 + lane], acc[j]);
            }
        }
        __syncthreads();
    }

    float* outp = pacc + ((size_t)(s * B_ + b) * H_ + w) * C_;
#pragma unroll
    for (int j = 0; j < 24; j++) outp[j * 32 + lane] = acc[j];
    if (lane == 0) pms[(size_t)(s * B_ + b) * H_ + w] = make_float2(m, ssum);
}

// ---------------- attention: combine partials -----------------------------
__global__ void __launch_bounds__(256) attn_comb_k(
    const float* __restrict__ pacc, const float2* __restrict__ pms,
    float* __restrict__ xbar)
{
    int b = blockIdx.x;
    int tid = threadIdx.x, w = tid >> 5, lane = tid & 31;
    float2 ms[SPLITS_];
    float wf[SPLITS_];
#pragma unroll
    for (int i = 0; i < SPLITS_; i++) ms[i] = pms[(size_t)(i * B_ + b) * H_ + w];
    float M = ms[0].x;
#pragma unroll
    for (int i = 1; i < SPLITS_; i++) M = fmaxf(M, ms[i].x);
    float S = 0.f;
#pragma unroll
    for (int i = 0; i < SPLITS_; i++) { wf[i] = __expf(ms[i].x - M); S += ms[i].y * wf[i]; }
    float inv = 1.f / S;
#pragma unroll
    for (int j = 0; j < 24; j++) {
        float v = 0.f;
#pragma unroll
        for (int i = 0; i < SPLITS_; i++)
            v += pacc[((size_t)(i * B_ + b) * H_ + w) * C_ + j * 32 + lane] * wf[i];
        xbar[((size_t)b * H_ + w) * C_ + j * 32 + lane] = v * inv;
    }
}

// ---------------- prompt rows into uP -------------------------------------
__global__ void copy_prompt_k(const float* __restrict__ prompt, float* __restrict__ uP)
{
    uP[(size_t)(B_ + blockIdx.x) * C_ + threadIdx.x] =
        prompt[(size_t)blockIdx.x * C_ + threadIdx.x];
}

// ---------------- gate + router-fc1 dots ----------------------------------
__global__ void __launch_bounds__(160) dots_k(
    const float* __restrict__ uP, const float* __restrict__ gate_w,
    const float* __restrict__ r1_w, float* __restrict__ gate_out,
    float* __restrict__ dr_out)
{
    int i = blockIdx.x;
    int w = threadIdx.x >> 5, lane = threadIdx.x & 31;
    const float* u = uP + (size_t)i * C_;
    const float* v = (w < 4) ? (gate_w + w * C_) : r1_w;
    float p = 0.f;
#pragma unroll
    for (int j = 0; j < 24; j++) p = fmaf(u[j * 32 + lane], v[j * 32 + lane], p);
#pragma unroll
    for (int o = 16; o; o >>= 1) p += __shfl_xor_sync(0xffffffffu, p, o);
    if (lane == 0) {
        if (w < 4) gate_out[i * E_ + w] = p;
        else       dr_out[i] = p;
    }
}

// ---------------- final combine per batch row -----------------------------
__global__ void __launch_bounds__(256) finale_k(
    const float* __restrict__ Yw, const float* __restrict__ gate,
    const float* __restrict__ dr, const float* __restrict__ gate_b,
    const float* __restrict__ exp_b, const float* __restrict__ r1_b,
    const float* __restrict__ r2_w, const float* __restrict__ r2_b,
    float* __restrict__ out)
{
    int b = blockIdx.x, tid = threadIdx.x;
    __shared__ float red[256];
    __shared__ float s_mr2, s_mrb;
    __shared__ float s_w[A_][E_];
    __shared__ float s_sc[A_];
    __shared__ float s_c1[E_];
    __shared__ float s_c2[A_][E_];

    float sum2 = 0.f, sumb = 0.f;
#pragma unroll
    for (int j = 0; j < 3; j++) {
        sum2 += r2_w[tid + j * 256];
        sumb += r2_b[tid + j * 256];
    }
    red[tid] = sum2; __syncthreads();
    for (int st = 128; st > 0; st >>= 1) { if (tid < st) red[tid] += red[tid + st]; __syncthreads(); }
    if (tid == 0) s_mr2 = red[0] * (1.f / C_);
    __syncthreads();
    red[tid] = sumb; __syncthreads();
    for (int st = 128; st > 0; st >>= 1) { if (tid < st) red[tid] += red[tid + st]; __syncthreads(); }
    if (tid == 0) s_mrb = red[0] * (1.f / C_);
    __syncthreads();

    if (tid < A_) {
        int a = tid;
        float g[E_];
#pragma unroll
        for (int e = 0; e < E_; e++)
            g[e] = gate[b * E_ + e] + gate[(B_ + a) * E_ + e] + gate_b[e];
        int mi = 0;
#pragma unroll
        for (int e = 1; e < E_; e++) if (g[e] < g[mi]) mi = e;
        float mx = -INFINITY;
#pragma unroll
        for (int e = 0; e < E_; e++) if (e != mi && g[e] > mx) mx = g[e];
        float ssum = 0.f, we[E_];
#pragma unroll
        for (int e = 0; e < E_; e++) {
            we[e] = (e == mi) ? 0.f : __expf(g[e] - mx);
            ssum += we[e];
        }
        float inv = 1.f / ssum;
#pragma unroll
        for (int e = 0; e < E_; e++) s_w[a][e] = we[e] * inv;
        float xv = dr[b] + dr[B_ + a] + r1_b[0];
        float hg = 0.5f * xv * (1.f + tanhf(0.7978845608028654f * (xv + 0.044715f * xv * xv * xv)));
        s_sc[a] = hg * s_mr2 + s_mrb;
    }
    __syncthreads();

    if (tid == 0) {
        bool excl[A_];
        for (int a = 0; a < A_; a++) excl[a] = false;
        for (int r = 0; r < 3; r++) {
            int mi = -1; float mv = INFINITY;
            for (int a = 0; a < A_; a++)
                if (!excl[a] && s_sc[a] < mv) { mv = s_sc[a]; mi = a; }
            excl[mi] = true;
        }
        float smax = -INFINITY;
        for (int a = 0; a < A_; a++) if (!excl[a] && s_sc[a] > smax) smax = s_sc[a];
        float ssum = 0.f, wt[A_];
        for (int a = 0; a < A_; a++) {
            wt[a] = excl[a] ? 0.f : __expf(s_sc[a] - smax);
            ssum += wt[a];
        }
        float inv = 1.f / ssum;
        for (int e = 0; e < E_; e++) {
            float c1 = 0.f;
            for (int a = 0; a < A_; a++) {
                float c2 = wt[a] * inv * s_w[a][e];
                s_c2[a][e] = c2;
                c1 += c2;
            }
            s_c1[e] = c1;
        }
    }
    __syncthreads();

#pragma unroll
    for (int j = 0; j < 3; j++) {
        int c = tid + j * 256;
        float v = 0.f;
#pragma unroll
        for (int e = 0; e < E_; e++)
            v += s_c1[e] * (Yw[(size_t)b * (E_ * C_) + e * C_ + c] + exp_b[e * C_ + c]);
#pragma unroll
        for (int a = 0; a < A_; a++)
#pragma unroll
            for (int e = 0; e < E_; e++)
                v += s_c2[a][e] * Yw[(size_t)(B_ + a) * (E_ * C_) + e * C_ + c];
        out[(size_t)b * C_ + c] = v;
    }
}

// ---------------- launcher -------------------------------------------------
extern "C" void kernel_launch(void* const* d_in, const int* in_sizes, int n_in,
                              void* d_out, int out_size)
{
    (void)in_sizes; (void)n_in; (void)out_size;
    const float* text   = (const float*)d_in[0];
    const float* vcls   = (const float*)d_in[1];
    const float* x      = (const float*)d_in[2];
    const float* prompt = (const float*)d_in[3];
    const float* Wq = (const float*)d_in[4];
    const float* bq = (const float*)d_in[5];
    const float* Wk = (const float*)d_in[6];
    // d_in[7] = bk : per-(b,h) constant logit shift -> softmax-invariant, unused
    const float* Wv = (const float*)d_in[8];
    const float* bv = (const float*)d_in[9];
    const float* Wo = (const float*)d_in[10];
    const float* bo = (const float*)d_in[11];
    const float* gate_w = (const float*)d_in[12];
    const float* gate_b = (const float*)d_in[13];
    const float* exp_w  = (const float*)d_in[14];
    const float* exp_b  = (const float*)d_in[15];
    const float* r1_w   = (const float*)d_in[16];
    const float* r1_b   = (const float*)d_in[17];
    const float* r2_w   = (const float*)d_in[18];
    const float* r2_b   = (const float*)d_in[19];
    float* out = (float*)d_out;

    void* p;
    cudaGetSymbolAddress(&p, g_qb);    float* qb    = (float*)p;
    cudaGetSymbolAddress(&p, g_qhat);  float* qhat  = (float*)p;
    cudaGetSymbolAddress(&p, g_xbar);  float* xbar  = (float*)p;
    cudaGetSymbolAddress(&p, g_o);     float* o     = (float*)p;
    cudaGetSymbolAddress(&p, g_uP);    float* uP    = (float*)p;
    cudaGetSymbolAddress(&p, g_Yw);    float* Yw    = (float*)p;
    cudaGetSymbolAddress(&p, g_gate);  float* gate  = (float*)p;
    cudaGetSymbolAddress(&p, g_dr);    float* dr    = (float*)p;
    cudaGetSymbolAddress(&p, g_pacc);  float* pacc  = (float*)p;
    cudaGetSymbolAddress(&p, g_pms);   float2* pms  = (float2*)p;

    // prompt rows of uP (independent)
    copy_prompt_k<<<A_, C_>>>(prompt, uP);

    // qb = text @ Wq^T + bq
    gemm_tc_k<true, true, false><<<dim3(12, 4, 1), 128>>>(
        B_, C_, C_, text, C_, 0, Wq, C_, 0, qb, C_, 0, bq, 0, nullptr, 0);

    // qhat[b,h,:] = Wk_h^T qb_h   (batched over h, K=96)
    gemm_tc_k<false, false, false><<<dim3(12, 4, 8), 128>>>(
        B_, C_, D_, qb, C_, D_, Wk, C_, D_ * C_, qhat, H_ * C_, C_,
        nullptr, 0, nullptr, 0);

    // attention partial pass (split-N 4, 4-stage cp.async) + combine
    attn_part_k<<<dim3(SPLITS_, B_), 256>>>(x, qhat, pacc, pms);
    attn_comb_k<<<B_, 256>>>(pacc, pms, xbar);

    // o[b, h*96+d] = Wv_h @ xbar[b,h] + bv_h   (batched over h)
    gemm_tc_k<true, true, false><<<dim3(2, 4, 8), 128>>>(
        B_, D_, C_, xbar, H_ * C_, C_, Wv, C_, D_ * C_, o, C_, D_,
        bv, D_, nullptr, 0);

    // uP rows 0..255: u = o @ Wo^T + bo + visual_cls
    gemm_tc_k<true, true, true><<<dim3(12, 4, 1), 128>>>(
        B_, C_, C_, o, C_, 0, Wo, C_, 0, uP, C_, 0, bo, 0, vcls, C_);

    // expert outputs: Yw[i, e*C+o] = uP[i] @ exp_w[e]^T
    gemm_tc_k<true, false, false><<<dim3(48, 5, 1), 128>>>(
        B_ + A_, E_ * C_, C_, uP, C_, 0, exp_w, C_, 0, Yw, E_ * C_, 0,
        nullptr, 0, nullptr, 0);

    // gate + router-fc1 dots (fp32)
    dots_k<<<B_ + A_, 160>>>(uP, gate_w, r1_w, gate, dr);

    // scores, top-k, softmax weights, weighted expert combine
    finale_k<<<B_, 256>>>(Yw, gate, dr, gate_b, exp_b, r1_b, r2_w, r2_b, out);
}